// round 1
// baseline (speedup 1.0000x reference)
#include <cuda_runtime.h>
#include <math.h>

#define Bq 16
#define Gq 32
#define Tq 4096
#define Dq 512
#define Kq 8
#define BG (Bq*Gq)          // 512
#define NWIN (Tq-3)         // 4093
#define NPAIR (NWIN-1)      // 4092
#define MPq 24
#define BINS 576            // 24*24

// ---------------- scratch (static device globals; no allocation) ----------------
__device__ float  g_pooled[BG*Tq];            // 8 MB
__device__ float  g_modes[(size_t)BG*Kq*Tq];  // 64 MB
__device__ float  g_filt[Kq*Tq];              // symmetric filters, bit-reversed order
__device__ float2 g_tw[Tq/2];                 // exp(-2*pi*i*m/T)
__device__ int    g_lut[64];                  // comparison key -> pattern id

// ---------------- init: twiddles, filters, pattern LUT ----------------
__device__ double filt_val(int idx, double cf) {
    double fr = (idx < Tq/2) ? (double)idx / Tq : (double)(idx - Tq) / Tq;
    double d = fabs(fr - cf) / 0.125;   // bandwidth = 1/K = 0.125
    return exp(-0.5 * d * d);
}

__global__ void init_tables() {
    int j = blockIdx.x * blockDim.x + threadIdx.x;   // 0..4095
    if (j < Tq/2) {
        float a = -(float)j / 2048.0f;               // angle / pi
        g_tw[j] = make_float2(cospif(a), sinpif(a));
    }
    if (j < Tq) {
        int f = __brev((unsigned)j) >> 20;           // bitrev12
        #pragma unroll
        for (int k = 0; k < Kq; k++) {
            double cf = -0.5 + (double)k / 7.0;      // linspace(-0.5, 0.5, 8)
            double gs = 0.5 * (filt_val(f, cf) + filt_val((Tq - f) & (Tq - 1), cf));
            g_filt[k*Tq + j] = (float)gs;
        }
    }
    if (j == 0) {
        for (int q = 0; q < 64; q++) g_lut[q] = 0;
        // enumerate all 24 rank assignments rk[i] = rank of w_i
        for (int r0 = 0; r0 < 4; r0++)
        for (int r1 = 0; r1 < 4; r1++) { if (r1 == r0) continue;
        for (int r2 = 0; r2 < 4; r2++) { if (r2 == r0 || r2 == r1) continue;
            int r3 = 6 - r0 - r1 - r2;
            int rk[4] = {r0, r1, r2, r3};
            int si[4];
            for (int i = 0; i < 4; i++) si[rk[i]] = i;   // argsort = inverse of ranks
            int key = (rk[0]>rk[1]) | ((rk[0]>rk[2])<<1) | ((rk[0]>rk[3])<<2)
                    | ((rk[1]>rk[2])<<3) | ((rk[1]>rk[3])<<4) | ((rk[2]>rk[3])<<5);
            int c0 = (si[0]>si[1]) + (si[0]>si[2]) + (si[0]>si[3]);
            int c1 = (si[1]>si[2]) + (si[1]>si[3]);
            int c2 = (si[2]>si[3]);
            g_lut[key] = 6*c0 + 2*c1 + c2;               // Lehmer code
        }}
    }
}

// ---------------- pooling: [B,T,D] -> [B,G,T], mean over 16 channels ----------------
__global__ void pool_kernel(const float* __restrict__ hs) {
    int warp = (blockIdx.x * blockDim.x + threadIdx.x) >> 5;
    int lane = threadIdx.x & 31;                         // lane == group (G==32, spg==16)
    if (warp >= Bq*Tq) return;
    int b = warp >> 12, t = warp & (Tq - 1);
    const float4* p = (const float4*)(hs + (size_t)warp * Dq + lane * 16);
    float4 a = p[0], c = p[1], d = p[2], e = p[3];
    float s = a.x+a.y+a.z+a.w + c.x+c.y+c.z+c.w + d.x+d.y+d.z+d.w + e.x+e.y+e.z+e.w;
    g_pooled[((size_t)b*Gq + lane)*Tq + t] = s * (1.0f/16.0f);
}

// ---------------- VMD: 1 fwd FFT + 4 packed inverse FFTs per (b,g) ----------------
__device__ __forceinline__ float2 cadd(float2 a, float2 b){ return make_float2(a.x+b.x, a.y+b.y); }
__device__ __forceinline__ float2 csub(float2 a, float2 b){ return make_float2(a.x-b.x, a.y-b.y); }

__global__ void __launch_bounds__(512, 2) vmd_kernel() {
    extern __shared__ float2 sh[];
    float2* buf = sh;            // 4096 complex
    float2* Xs  = sh + 4096;     // 4096 complex (spectrum, bit-reversed)
    float2* stw = sh + 8192;     // 2048 twiddles
    const int bg  = blockIdx.x;
    const int tid = threadIdx.x;

    for (int i = tid; i < Tq/2; i += 512) stw[i] = g_tw[i];
    const float* sig = g_pooled + (size_t)bg * Tq;
    for (int i = tid; i < Tq; i += 512) buf[i] = make_float2(sig[i], 0.0f);
    __syncthreads();

    // forward DIF (natural in -> bit-reversed out), twiddle exp = -2*pi*j*(2048/h)/4096
    for (int h = 2048; h >= 1; h >>= 1) {
        int tms = 2048 / h;
        #pragma unroll 4
        for (int u = tid; u < 2048; u += 512) {
            int j = u & (h - 1);
            int i = ((u ^ j) << 1) | j;
            float2 a = buf[i], b = buf[i + h];
            float2 s = cadd(a, b), d = csub(a, b);
            float2 w = stw[j * tms];
            buf[i]     = s;
            buf[i + h] = make_float2(d.x*w.x - d.y*w.y, d.x*w.y + d.y*w.x);
        }
        __syncthreads();
    }
    for (int i = tid; i < Tq; i += 512) Xs[i] = buf[i];
    __syncthreads();

    float* mo = g_modes + (size_t)bg * Kq * Tq;
    for (int p = 0; p < 4; p++) {
        const float* fr = g_filt + (2*p)   * Tq;
        const float* fi = g_filt + (2*p+1) * Tq;
        for (int i = tid; i < Tq; i += 512) {
            float2 x = Xs[i];
            float gr = fr[i], gi = fi[i];
            buf[i] = make_float2(x.x*gr - x.y*gi, x.x*gi + x.y*gr);
        }
        __syncthreads();
        // inverse DIT (bit-reversed in -> natural out), conjugate twiddles
        for (int h = 1; h <= 2048; h <<= 1) {
            int tms = 2048 / h;
            #pragma unroll 4
            for (int u = tid; u < 2048; u += 512) {
                int j = u & (h - 1);
                int i = ((u ^ j) << 1) | j;
                float2 a = buf[i], b = buf[i + h];
                float2 w = stw[j * tms];
                float2 bw = make_float2(b.x*w.x + b.y*w.y, b.y*w.x - b.x*w.y); // b*conj(w)
                buf[i]     = cadd(a, bw);
                buf[i + h] = csub(a, bw);
            }
            __syncthreads();
        }
        const float inv = 1.0f / Tq;
        for (int i = tid; i < Tq; i += 512) {
            float2 y = buf[i];
            mo[(size_t)(2*p)*Tq + i]     = y.x * inv;   // mode 2p
            mo[(size_t)(2*p+1)*Tq + i]   = y.y * inv;   // mode 2p+1
        }
        __syncthreads();
    }
}

// ---------------- tmptm: ordinal-pattern transition histogram ----------------
__global__ void tmptm_kernel(float* __restrict__ out) {
    __shared__ float srow[Tq];
    __shared__ int   hist[BINS];
    __shared__ int   lut[64];
    const int bg = blockIdx.x, tid = threadIdx.x;   // 256 threads
    for (int i = tid; i < BINS; i += 256) hist[i] = 0;
    if (tid < 64) lut[tid] = g_lut[tid];
    __syncthreads();

    for (int k = 0; k < Kq; k++) {
        const float* mo = g_modes + ((size_t)bg * Kq + k) * Tq;
        for (int i = tid; i < Tq; i += 256) srow[i] = mo[i];
        __syncthreads();

        int n0 = tid * 16;
        int n1 = min(n0 + 16, NPAIR);
        // key bits: b01,b02,b03,b12,b13,b23 at bits 0..5 (b_ij = w_i > w_j)
        float w0 = srow[n0], w1 = srow[n0+1], w2 = srow[n0+2], w3 = srow[n0+3];
        int key = (w0>w1) | ((w0>w2)<<1) | ((w0>w3)<<2)
                | ((w1>w2)<<3) | ((w1>w3)<<4) | ((w2>w3)<<5);
        int prev = lut[key];
        for (int n = n0 + 1; n <= n1; n++) {
            float w4 = srow[n + 3];
            int nb0 = (w1 > w4), nb1 = (w2 > w4), nb2 = (w3 > w4);
            key = ((key >> 3) & 1) | (((key >> 4) & 1) << 1) | (nb0 << 2)
                | (((key >> 5) & 1) << 3) | (nb1 << 4) | (nb2 << 5);
            int cur = lut[key];
            atomicAdd(&hist[prev * MPq + cur], 1);
            prev = cur;
            w1 = w2; w2 = w3; w3 = w4;
        }
        __syncthreads();
    }
    const float invs = 1.0f / (float)(Kq * NPAIR);  // row sum is constant 32736
    for (int i = tid; i < BINS; i += 256)
        out[(size_t)bg * BINS + i] = (float)hist[i] * invs;
}

// ---------------- fmptm: energy correlations, upper triangle ----------------
__global__ void fmptm_kernel(float* __restrict__ out) {
    const int bg = blockIdx.x, tid = threadIdx.x;   // 256 threads
    const float* mo = g_modes + (size_t)bg * Kq * Tq;
    float s1[Kq]; float s2[36];
    #pragma unroll
    for (int i = 0; i < Kq; i++) s1[i] = 0.0f;
    #pragma unroll
    for (int i = 0; i < 36; i++) s2[i] = 0.0f;

    for (int t = tid; t < Tq; t += 256) {
        float e[Kq];
        #pragma unroll
        for (int k = 0; k < Kq; k++) {
            float m = mo[(size_t)k * Tq + t];
            e[k] = m * m;
            s1[k] += e[k];
        }
        int idx = 0;
        #pragma unroll
        for (int k = 0; k < Kq; k++)
            #pragma unroll
            for (int l = k; l < Kq; l++)
                s2[idx++] += e[k] * e[l];
    }

    __shared__ float red[44];
    if (tid < 44) red[tid] = 0.0f;
    __syncthreads();
    #pragma unroll
    for (int i = 0; i < Kq; i++) {
        float v = s1[i];
        #pragma unroll
        for (int o = 16; o; o >>= 1) v += __shfl_down_sync(0xffffffffu, v, o);
        if ((tid & 31) == 0) atomicAdd(&red[i], v);
    }
    #pragma unroll
    for (int i = 0; i < 36; i++) {
        float v = s2[i];
        #pragma unroll
        for (int o = 16; o; o >>= 1) v += __shfl_down_sync(0xffffffffu, v, o);
        if ((tid & 31) == 0) atomicAdd(&red[8 + i], v);
    }
    __syncthreads();

    if (tid < 28) {
        int k = 0, rem = tid;
        while (rem >= 7 - k) { rem -= 7 - k; k++; }
        int l = k + 1 + rem;
        float S1k = red[k], S1l = red[l];
        int dk = 8 + (k * (17 - k)) / 2;
        int dl = 8 + (l * (17 - l)) / 2;
        float S2kk = red[dk], S2ll = red[dl];
        int off = k * 8 - (k * (k - 1)) / 2 + (l - k);
        float S2kl = red[8 + off];
        const float Tf = (float)Tq;
        float vk = (S2kk - S1k * S1k / Tf) / (Tf - 1.0f);
        float vl = (S2ll - S1l * S1l / Tf) / (Tf - 1.0f);
        float sk = fmaxf(sqrtf(fmaxf(vk, 0.0f)), 1e-8f);
        float sl = fmaxf(sqrtf(fmaxf(vl, 0.0f)), 1e-8f);
        float corr = (S2kl - S1k * S1l / Tf) / (Tf * sk * sl);
        out[(size_t)bg * 28 + tid] = corr;
    }
}

// ---------------- launch ----------------
extern "C" void kernel_launch(void* const* d_in, const int* in_sizes, int n_in,
                              void* d_out, int out_size) {
    const float* hs = (const float*)d_in[0];
    float* out = (float*)d_out;

    init_tables<<<16, 256>>>();
    pool_kernel<<<(Bq*Tq*32)/256, 256>>>(hs);   // 8192 blocks, 1 warp per (b,t)

    cudaFuncSetAttribute(vmd_kernel, cudaFuncAttributeMaxDynamicSharedMemorySize, 81920);
    vmd_kernel<<<BG, 512, 81920>>>();

    tmptm_kernel<<<BG, 256>>>(out);                       // [B,G,576]
    fmptm_kernel<<<BG, 256>>>(out + (size_t)BG * BINS);   // [B,G,28]
}

// round 2
// speedup vs baseline: 1.1278x; 1.1278x over previous
#include <cuda_runtime.h>
#include <math.h>

#define Bq 16
#define Gq 32
#define Tq 4096
#define Dq 512
#define Kq 8
#define BG (Bq*Gq)          // 512
#define NWIN (Tq-3)         // 4093
#define NPAIR (NWIN-1)      // 4092
#define MPq 24
#define BINS 576

// ---------------- constant tables (device globals) ----------------
__device__ float  g_filt[Kq*Tq];   // symmetric filters, digit-reversed(base4) order, /4096 folded in
__device__ float2 g_tw[Tq/2];      // exp(-2*pi*i*m/4096), m=0..2047
__device__ int    g_lut[64];       // 6-bit comparison key -> Lehmer pattern id

// ---------------- helpers ----------------
__device__ __forceinline__ int swb(int e){ return e ^ ((e >> 4) & 3); }   // data swizzle
__device__ __forceinline__ int swt(int m){ return m ^ ((m >> 4) & 15); }  // twiddle swizzle
__device__ __forceinline__ float2 cadd(float2 a, float2 b){ return make_float2(a.x+b.x, a.y+b.y); }
__device__ __forceinline__ float2 csub(float2 a, float2 b){ return make_float2(a.x-b.x, a.y-b.y); }
__device__ __forceinline__ float2 cmul(float2 a, float2 b){ return make_float2(a.x*b.x - a.y*b.y, a.x*b.y + a.y*b.x); }
__device__ __forceinline__ float2 cmulc(float2 a, float2 b){ return make_float2(a.x*b.x + a.y*b.y, a.y*b.x - a.x*b.y); } // a*conj(b)

// ---------------- init: twiddles, filters (digit-reversed), pattern LUT ----------------
__device__ double filt_val(int idx, double cf) {
    double fr = (idx < Tq/2) ? (double)idx / Tq : (double)(idx - Tq) / Tq;
    double d = fabs(fr - cf) / 0.125;   // bandwidth = 1/K
    return exp(-0.5 * d * d);
}

__global__ void init_tables() {
    int j = blockIdx.x * blockDim.x + threadIdx.x;   // 0..4095
    if (j < Tq/2) {
        float a = -(float)j / 2048.0f;
        g_tw[j] = make_float2(cospif(a), sinpif(a));
    }
    if (j < Tq) {
        // base-4 digit reversal of 12-bit index
        int f = 0, x = j;
        #pragma unroll
        for (int d = 0; d < 6; d++) { f = (f << 2) | (x & 3); x >>= 2; }
        #pragma unroll
        for (int k = 0; k < Kq; k++) {
            double cf = -0.5 + (double)k / 7.0;
            double gs = 0.5 * (filt_val(f, cf) + filt_val((Tq - f) & (Tq - 1), cf));
            g_filt[k*Tq + j] = (float)(gs / (double)Tq);   // fold 1/T of IFFT
        }
    }
    if (j == 0) {
        for (int q = 0; q < 64; q++) g_lut[q] = 0;
        for (int r0 = 0; r0 < 4; r0++)
        for (int r1 = 0; r1 < 4; r1++) { if (r1 == r0) continue;
        for (int r2 = 0; r2 < 4; r2++) { if (r2 == r0 || r2 == r1) continue;
            int r3 = 6 - r0 - r1 - r2;
            int rk[4] = {r0, r1, r2, r3};
            int si[4];
            for (int i = 0; i < 4; i++) si[rk[i]] = i;
            int key = (rk[0]>rk[1]) | ((rk[0]>rk[2])<<1) | ((rk[0]>rk[3])<<2)
                    | ((rk[1]>rk[2])<<3) | ((rk[1]>rk[3])<<4) | ((rk[2]>rk[3])<<5);
            int c0 = (si[0]>si[1]) + (si[0]>si[2]) + (si[0]>si[3]);
            int c1 = (si[1]>si[2]) + (si[1]>si[3]);
            int c2 = (si[2]>si[3]);
            g_lut[key] = 6*c0 + 2*c1 + c2;
        }}
    }
}

// ---------------- fused kernel: pool + FFT + VMD + tmptm + fmptm ----------------
// dynamic smem: pairs[4][4096] float2 (128KB) + Xs[4096] float2 (32KB) + stw[2048] float2 (16KB)
#define DSMEM ((4*Tq + Tq + Tq/2) * 8)

__global__ void __launch_bounds__(512, 1) fused_kernel(const float* __restrict__ hs,
                                                       float* __restrict__ out) {
    extern __shared__ float2 sh[];
    float2* pairs = sh;               // 4 * 4096 (modes 2p, 2p+1 as .x/.y)
    float2* Xs    = sh + 4*Tq;        // spectrum (digit-reversed, swizzled)
    float2* stw   = sh + 5*Tq;        // twiddles (swizzled)

    __shared__ int lut[64];
    __shared__ int hist[4*BINS];
    __shared__ unsigned char spid[2][Tq];
    __shared__ float red[44];

    const int bg  = blockIdx.x;
    const int tid = threadIdx.x;
    const int wid = tid >> 5;
    const int lane = tid & 31;
    const int b = bg >> 5, g = bg & 31;

    // --- table loads / clears ---
    for (int m = tid; m < Tq/2; m += 512) stw[swt(m)] = g_tw[m];
    if (tid < 64) lut[tid] = g_lut[tid];
    for (int i = tid; i < 4*BINS; i += 512) hist[i] = 0;
    if (tid < 44) red[tid] = 0.0f;

    // --- pooling: mean of 16 channels of group g -> pairs[0] (as complex) ---
    const float* src = hs + ((size_t)b * Tq) * Dq + g * 16;
    for (int t = tid; t < Tq; t += 512) {
        const float4* p = (const float4*)(src + (size_t)t * Dq);
        float4 a = p[0], c = p[1], d = p[2], e = p[3];
        float s = a.x+a.y+a.z+a.w + c.x+c.y+c.z+c.w + d.x+d.y+d.z+d.w + e.x+e.y+e.z+e.w;
        pairs[swb(t)] = make_float2(s * (1.0f/16.0f), 0.0f);
    }
    __syncthreads();

    // --- forward radix-4 DIF FFT (natural -> digit-reversed) in pairs[0] ---
    {
        float2* buf = pairs;
        for (int h = 1024; h >= 1; h >>= 2) {
            int tm = 1024 / h;
            #pragma unroll 2
            for (int u = tid; u < 1024; u += 512) {
                int j = u & (h - 1);
                int i = ((u - j) << 2) + j;
                float2 x0 = buf[swb(i)],       x1 = buf[swb(i + h)];
                float2 x2 = buf[swb(i + 2*h)], x3 = buf[swb(i + 3*h)];
                float2 p02 = cadd(x0, x2), m02 = csub(x0, x2);
                float2 p13 = cadd(x1, x3), m13 = csub(x1, x3);
                float2 y0 = cadd(p02, p13);
                float2 y2 = csub(p02, p13);
                float2 y1 = make_float2(m02.x + m13.y, m02.y - m13.x);  // m02 - i*m13
                float2 y3 = make_float2(m02.x - m13.y, m02.y + m13.x);  // m02 + i*m13
                int m1 = j * tm;
                float2 w1 = stw[swt(m1)], w2 = stw[swt(2*m1)];
                float2 w3 = cmul(w1, w2);
                buf[swb(i)]       = y0;
                buf[swb(i + h)]   = cmul(y1, w1);
                buf[swb(i + 2*h)] = cmul(y2, w2);
                buf[swb(i + 3*h)] = cmul(y3, w3);
            }
            __syncthreads();
        }
        // save spectrum
        for (int e = tid; e < Tq; e += 512) Xs[e] = buf[e];
        __syncthreads();
    }

    // --- 4 packed inverse FFTs: filter (2 real symmetric filters as complex) then radix-4 DIT ---
    for (int p = 0; p < 4; p++) {
        float2* W = pairs + p * Tq;
        const float* fr = g_filt + (2*p)   * Tq;
        const float* fi = g_filt + (2*p+1) * Tq;
        for (int e = tid; e < Tq; e += 512) {
            float2 x = Xs[swb(e)];
            float gr = fr[e], gi = fi[e];
            W[swb(e)] = make_float2(x.x*gr - x.y*gi, x.x*gi + x.y*gr);
        }
        __syncthreads();
        for (int h = 1; h <= 1024; h <<= 2) {
            int tm = 1024 / h;
            #pragma unroll 2
            for (int u = tid; u < 1024; u += 512) {
                int j = u & (h - 1);
                int i = ((u - j) << 2) + j;
                int m1 = j * tm;
                float2 w1 = stw[swt(m1)], w2 = stw[swt(2*m1)];
                float2 w3 = cmul(w1, w2);
                float2 x0 = W[swb(i)];
                float2 x1 = cmulc(W[swb(i + h)],   w1);
                float2 x2 = cmulc(W[swb(i + 2*h)], w2);
                float2 x3 = cmulc(W[swb(i + 3*h)], w3);
                float2 p02 = cadd(x0, x2), m02 = csub(x0, x2);
                float2 p13 = cadd(x1, x3), m13 = csub(x1, x3);
                W[swb(i)]       = cadd(p02, p13);
                W[swb(i + 2*h)] = csub(p02, p13);
                W[swb(i + h)]   = make_float2(m02.x - m13.y, m02.y + m13.x);  // m02 + i*m13
                W[swb(i + 3*h)] = make_float2(m02.x + m13.y, m02.y - m13.x);  // m02 - i*m13
            }
            __syncthreads();
        }
    }
    // modes now resident: mode (2p+c) at t = pairs[p*Tq + swb(t)].x/.y  (already scaled by 1/T)

    // --- fmptm: raw-moment accumulation from shared modes ---
    {
        float s1[Kq]; float s2[36];
        #pragma unroll
        for (int i = 0; i < Kq; i++) s1[i] = 0.0f;
        #pragma unroll
        for (int i = 0; i < 36; i++) s2[i] = 0.0f;
        for (int t = tid; t < Tq; t += 512) {
            int st = swb(t);
            float e[Kq];
            #pragma unroll
            for (int p = 0; p < 4; p++) {
                float2 v = pairs[p*Tq + st];
                e[2*p]   = v.x * v.x;
                e[2*p+1] = v.y * v.y;
            }
            #pragma unroll
            for (int k = 0; k < Kq; k++) s1[k] += e[k];
            int idx = 0;
            #pragma unroll
            for (int k = 0; k < Kq; k++)
                #pragma unroll
                for (int l = k; l < Kq; l++)
                    s2[idx++] += e[k] * e[l];
        }
        #pragma unroll
        for (int i = 0; i < Kq; i++) {
            float v = s1[i];
            #pragma unroll
            for (int o = 16; o; o >>= 1) v += __shfl_down_sync(0xffffffffu, v, o);
            if (lane == 0) atomicAdd(&red[i], v);
        }
        #pragma unroll
        for (int i = 0; i < 36; i++) {
            float v = s2[i];
            #pragma unroll
            for (int o = 16; o; o >>= 1) v += __shfl_down_sync(0xffffffffu, v, o);
            if (lane == 0) atomicAdd(&red[8 + i], v);
        }
    }

    // --- tmptm: ordinal pattern ids + transition histogram (match-aggregated atomics) ---
    for (int p = 0; p < 4; p++) {
        float2* W = pairs + p * Tq;
        __syncthreads();   // protect spid reuse from previous iteration's hist pass
        for (int n = tid; n < NWIN; n += 512) {
            float2 a = W[swb(n)], bb = W[swb(n+1)], c = W[swb(n+2)], d = W[swb(n+3)];
            int kx = (a.x>bb.x) | ((a.x>c.x)<<1) | ((a.x>d.x)<<2)
                   | ((bb.x>c.x)<<3) | ((bb.x>d.x)<<4) | ((c.x>d.x)<<5);
            int ky = (a.y>bb.y) | ((a.y>c.y)<<1) | ((a.y>d.y)<<2)
                   | ((bb.y>c.y)<<3) | ((bb.y>d.y)<<4) | ((c.y>d.y)<<5);
            spid[0][n] = (unsigned char)lut[kx];
            spid[1][n] = (unsigned char)lut[ky];
        }
        __syncthreads();
        int* myhist = hist + (wid & 3) * BINS;
        #pragma unroll
        for (int it = 0; it < 8; it++) {
            int idx = it * 512 + tid;
            bool valid = (idx < NPAIR);
            #pragma unroll
            for (int c = 0; c < 2; c++) {
                int lin;
                if (valid) lin = (int)spid[c][idx] * MPq + (int)spid[c][idx+1];
                else       lin = BINS + lane;            // unique dummy, never merges
                unsigned msk = __match_any_sync(0xffffffffu, lin);
                int lead = __ffs(msk) - 1;
                if (valid && lane == lead)
                    atomicAdd(&myhist[lin], __popc(msk));
            }
        }
    }
    __syncthreads();

    // --- outputs ---
    const float invs = 1.0f / (float)(Kq * NPAIR);   // row sum is constant
    for (int i = tid; i < BINS; i += 512) {
        int s = hist[i] + hist[BINS + i] + hist[2*BINS + i] + hist[3*BINS + i];
        out[(size_t)bg * BINS + i] = (float)s * invs;
    }
    if (tid < 28) {
        float* out2 = out + (size_t)BG * BINS;
        int k = 0, rem = tid;
        while (rem >= 7 - k) { rem -= 7 - k; k++; }
        int l = k + 1 + rem;
        float S1k = red[k], S1l = red[l];
        int dk = 8 + (k * (17 - k)) / 2;
        int dl = 8 + (l * (17 - l)) / 2;
        float S2kk = red[dk], S2ll = red[dl];
        int off = k * 8 - (k * (k - 1)) / 2 + (l - k);
        float S2kl = red[8 + off];
        const float Tf = (float)Tq;
        float vk = (S2kk - S1k * S1k / Tf) / (Tf - 1.0f);
        float vl = (S2ll - S1l * S1l / Tf) / (Tf - 1.0f);
        float sk = fmaxf(sqrtf(fmaxf(vk, 0.0f)), 1e-8f);
        float sl = fmaxf(sqrtf(fmaxf(vl, 0.0f)), 1e-8f);
        float corr = (S2kl - S1k * S1l / Tf) / (Tf * sk * sl);
        out2[(size_t)bg * 28 + tid] = corr;
    }
}

// ---------------- launch ----------------
extern "C" void kernel_launch(void* const* d_in, const int* in_sizes, int n_in,
                              void* d_out, int out_size) {
    const float* hs = (const float*)d_in[0];
    float* out = (float*)d_out;

    init_tables<<<16, 256>>>();
    cudaFuncSetAttribute(fused_kernel, cudaFuncAttributeMaxDynamicSharedMemorySize, DSMEM);
    fused_kernel<<<BG, 512, DSMEM>>>(hs, out);
}

// round 3
// speedup vs baseline: 1.5295x; 1.3562x over previous
#include <cuda_runtime.h>
#include <math.h>

#define Bq 16
#define Gq 32
#define Tq 4096
#define Dq 512
#define Kq 8
#define BG (Bq*Gq)          // 512
#define NWIN (Tq-3)         // 4093
#define NPAIR (NWIN-1)      // 4092
#define MPq 24
#define BINS 576

// ---------------- tables + scratch (device globals; no allocation) ----------------
__device__ float  g_filt[Kq*Tq];            // symmetric filters, digit-reversed(base4), /4096 folded
__device__ float2 g_tw[Tq/2];               // exp(-2*pi*i*m/4096)
__device__ int    g_lut[64];                // 6-bit comparison key -> Lehmer pattern id
__device__ float2 g_spec[(size_t)BG*Tq];    // 16 MB spectrum (physical/swizzled layout)
__device__ float  g_energy[(size_t)BG*Kq*Tq]; // 64 MB mode energies
__device__ int    g_hist[BG*BINS];          // 1.18 MB transition counts

// ---------------- helpers ----------------
__device__ __forceinline__ int swb(int e){ return e ^ ((e >> 4) & 3); }
__device__ __forceinline__ int swt(int m){ return m ^ ((m >> 4) & 15); }
__device__ __forceinline__ float2 cadd(float2 a, float2 b){ return make_float2(a.x+b.x, a.y+b.y); }
__device__ __forceinline__ float2 csub(float2 a, float2 b){ return make_float2(a.x-b.x, a.y-b.y); }
__device__ __forceinline__ float2 cmul(float2 a, float2 b){ return make_float2(a.x*b.x - a.y*b.y, a.x*b.y + a.y*b.x); }
__device__ __forceinline__ float2 cmulc(float2 a, float2 b){ return make_float2(a.x*b.x + a.y*b.y, a.y*b.x - a.x*b.y); }

// ---------------- init ----------------
__device__ double filt_val(int idx, double cf) {
    double fr = (idx < Tq/2) ? (double)idx / Tq : (double)(idx - Tq) / Tq;
    double d = fabs(fr - cf) / 0.125;
    return exp(-0.5 * d * d);
}

__global__ void init_tables() {
    int j = blockIdx.x * blockDim.x + threadIdx.x;
    if (j < Tq/2) {
        float a = -(float)j / 2048.0f;
        g_tw[j] = make_float2(cospif(a), sinpif(a));
    }
    if (j < Tq) {
        int f = 0, x = j;
        #pragma unroll
        for (int d = 0; d < 6; d++) { f = (f << 2) | (x & 3); x >>= 2; }
        #pragma unroll
        for (int k = 0; k < Kq; k++) {
            double cf = -0.5 + (double)k / 7.0;
            double gs = 0.5 * (filt_val(f, cf) + filt_val((Tq - f) & (Tq - 1), cf));
            g_filt[k*Tq + j] = (float)(gs / (double)Tq);
        }
    }
    if (j == 0) {
        for (int q = 0; q < 64; q++) g_lut[q] = 0;
        for (int r0 = 0; r0 < 4; r0++)
        for (int r1 = 0; r1 < 4; r1++) { if (r1 == r0) continue;
        for (int r2 = 0; r2 < 4; r2++) { if (r2 == r0 || r2 == r1) continue;
            int r3 = 6 - r0 - r1 - r2;
            int rk[4] = {r0, r1, r2, r3};
            int si[4];
            for (int i = 0; i < 4; i++) si[rk[i]] = i;
            int key = (rk[0]>rk[1]) | ((rk[0]>rk[2])<<1) | ((rk[0]>rk[3])<<2)
                    | ((rk[1]>rk[2])<<3) | ((rk[1]>rk[3])<<4) | ((rk[2]>rk[3])<<5);
            int c0 = (si[0]>si[1]) + (si[0]>si[2]) + (si[0]>si[3]);
            int c1 = (si[1]>si[2]) + (si[1]>si[3]);
            int c2 = (si[2]>si[3]);
            g_lut[key] = 6*c0 + 2*c1 + c2;
        }}
    }
}

// ---------------- kernel A: pool + forward FFT -> g_spec; zero g_hist ----------------
#define ASMEM ((Tq + Tq/2) * 8)   // buf 4096 float2 + stw 2048 float2 = 48KB

__global__ void __launch_bounds__(512, 2) fwd_kernel(const float* __restrict__ hs) {
    extern __shared__ float2 sh[];
    float2* buf = sh;
    float2* stw = sh + Tq;
    const int bg  = blockIdx.x;
    const int tid = threadIdx.x;
    const int b = bg >> 5, g = bg & 31;

    for (int m = tid; m < Tq/2; m += 512) stw[swt(m)] = g_tw[m];
    for (int i = tid; i < BINS; i += 512) g_hist[bg*BINS + i] = 0;

    const float* src = hs + ((size_t)b * Tq) * Dq + g * 16;
    for (int t = tid; t < Tq; t += 512) {
        const float4* p = (const float4*)(src + (size_t)t * Dq);
        float4 a = p[0], c = p[1], d = p[2], e = p[3];
        float s = a.x+a.y+a.z+a.w + c.x+c.y+c.z+c.w + d.x+d.y+d.z+d.w + e.x+e.y+e.z+e.w;
        buf[swb(t)] = make_float2(s * (1.0f/16.0f), 0.0f);
    }
    __syncthreads();

    for (int h = 1024; h >= 1; h >>= 2) {
        int tm = 1024 / h;
        #pragma unroll 2
        for (int u = tid; u < 1024; u += 512) {
            int j = u & (h - 1);
            int i = ((u - j) << 2) + j;
            float2 x0 = buf[swb(i)],       x1 = buf[swb(i + h)];
            float2 x2 = buf[swb(i + 2*h)], x3 = buf[swb(i + 3*h)];
            float2 p02 = cadd(x0, x2), m02 = csub(x0, x2);
            float2 p13 = cadd(x1, x3), m13 = csub(x1, x3);
            float2 y0 = cadd(p02, p13);
            float2 y2 = csub(p02, p13);
            float2 y1 = make_float2(m02.x + m13.y, m02.y - m13.x);
            float2 y3 = make_float2(m02.x - m13.y, m02.y + m13.x);
            int m1 = j * tm;
            float2 w1 = stw[swt(m1)], w2 = stw[swt(2*m1)];
            float2 w3 = cmul(w1, w2);
            buf[swb(i)]       = y0;
            buf[swb(i + h)]   = cmul(y1, w1);
            buf[swb(i + 2*h)] = cmul(y2, w2);
            buf[swb(i + 3*h)] = cmul(y3, w3);
        }
        __syncthreads();
    }
    float2* dst = g_spec + (size_t)bg * Tq;
    for (int i = tid; i < Tq; i += 512) dst[i] = buf[i];
}

// ---------------- kernel B: filter + inverse FFT + energies + tmptm ----------------
#define BSMEM ((Tq + Tq/2) * 8)   // W 4096 float2 + stw 2048 float2 = 48KB

__global__ void __launch_bounds__(512, 2) pair_kernel() {
    extern __shared__ float2 sh[];
    float2* W   = sh;
    float2* stw = sh + Tq;
    __shared__ int lut[64];
    __shared__ int hist[2*BINS];
    __shared__ unsigned char spid[2][Tq];

    const int bg  = blockIdx.x >> 2;
    const int p   = blockIdx.x & 3;
    const int tid = threadIdx.x;
    const int wid = tid >> 5;
    const int lane = tid & 31;

    for (int m = tid; m < Tq/2; m += 512) stw[swt(m)] = g_tw[m];
    if (tid < 64) lut[tid] = g_lut[tid];
    for (int i = tid; i < 2*BINS; i += 512) hist[i] = 0;

    // filter: pack two real symmetric filters into one complex spectrum
    const float2* Xg = g_spec + (size_t)bg * Tq;
    const float* fr = g_filt + (2*p)   * Tq;
    const float* fi = g_filt + (2*p+1) * Tq;
    for (int e = tid; e < Tq; e += 512) {
        float2 x = Xg[swb(e)];
        float gr = fr[e], gi = fi[e];
        W[swb(e)] = make_float2(x.x*gr - x.y*gi, x.x*gi + x.y*gr);
    }
    __syncthreads();

    // inverse radix-4 DIT
    for (int h = 1; h <= 1024; h <<= 2) {
        int tm = 1024 / h;
        #pragma unroll 2
        for (int u = tid; u < 1024; u += 512) {
            int j = u & (h - 1);
            int i = ((u - j) << 2) + j;
            int m1 = j * tm;
            float2 w1 = stw[swt(m1)], w2 = stw[swt(2*m1)];
            float2 w3 = cmul(w1, w2);
            float2 x0 = W[swb(i)];
            float2 x1 = cmulc(W[swb(i + h)],   w1);
            float2 x2 = cmulc(W[swb(i + 2*h)], w2);
            float2 x3 = cmulc(W[swb(i + 3*h)], w3);
            float2 p02 = cadd(x0, x2), m02 = csub(x0, x2);
            float2 p13 = cadd(x1, x3), m13 = csub(x1, x3);
            W[swb(i)]       = cadd(p02, p13);
            W[swb(i + 2*h)] = csub(p02, p13);
            W[swb(i + h)]   = make_float2(m02.x - m13.y, m02.y + m13.x);
            W[swb(i + 3*h)] = make_float2(m02.x + m13.y, m02.y - m13.x);
        }
        __syncthreads();
    }

    // energies out (modes 2p, 2p+1)
    float* e0 = g_energy + ((size_t)bg * Kq + 2*p)     * Tq;
    float* e1 = g_energy + ((size_t)bg * Kq + 2*p + 1) * Tq;
    for (int t = tid; t < Tq; t += 512) {
        float2 v = W[swb(t)];
        e0[t] = v.x * v.x;
        e1[t] = v.y * v.y;
    }

    // tmptm pass 1: pattern ids for both channels
    for (int n = tid; n < NWIN; n += 512) {
        float2 a = W[swb(n)], bb = W[swb(n+1)], c = W[swb(n+2)], d = W[swb(n+3)];
        int kx = (a.x>bb.x) | ((a.x>c.x)<<1) | ((a.x>d.x)<<2)
               | ((bb.x>c.x)<<3) | ((bb.x>d.x)<<4) | ((c.x>d.x)<<5);
        int ky = (a.y>bb.y) | ((a.y>c.y)<<1) | ((a.y>d.y)<<2)
               | ((bb.y>c.y)<<3) | ((bb.y>d.y)<<4) | ((c.y>d.y)<<5);
        spid[0][n] = (unsigned char)lut[kx];
        spid[1][n] = (unsigned char)lut[ky];
    }
    __syncthreads();

    // tmptm pass 2: transitions with warp-aggregated shared atomics
    int* myhist = hist + (wid & 1) * BINS;
    #pragma unroll
    for (int it = 0; it < 8; it++) {
        int idx = it * 512 + tid;
        bool valid = (idx < NPAIR);
        #pragma unroll
        for (int c = 0; c < 2; c++) {
            int lin;
            if (valid) lin = (int)spid[c][idx] * MPq + (int)spid[c][idx+1];
            else       lin = BINS + lane;
            unsigned msk = __match_any_sync(0xffffffffu, lin);
            int lead = __ffs(msk) - 1;
            if (valid && lane == lead)
                atomicAdd(&myhist[lin], __popc(msk));
        }
    }
    __syncthreads();

    // merge to global (int atomics: deterministic)
    for (int i = tid; i < BINS; i += 512) {
        int s = hist[i] + hist[BINS + i];
        if (s) atomicAdd(&g_hist[bg*BINS + i], s);
    }
}

// ---------------- kernel C: hist normalize + fmptm ----------------
__global__ void final_kernel(float* __restrict__ out) {
    const int bg = blockIdx.x, tid = threadIdx.x;   // 256 threads
    const float invs = 1.0f / (float)(Kq * NPAIR);
    for (int i = tid; i < BINS; i += 256)
        out[(size_t)bg * BINS + i] = (float)g_hist[bg*BINS + i] * invs;

    const float* eg = g_energy + (size_t)bg * Kq * Tq;
    float s1[Kq]; float s2[36];
    #pragma unroll
    for (int i = 0; i < Kq; i++) s1[i] = 0.0f;
    #pragma unroll
    for (int i = 0; i < 36; i++) s2[i] = 0.0f;

    for (int t = tid; t < Tq; t += 256) {
        float e[Kq];
        #pragma unroll
        for (int k = 0; k < Kq; k++) {
            e[k] = eg[(size_t)k * Tq + t];
            s1[k] += e[k];
        }
        int idx = 0;
        #pragma unroll
        for (int k = 0; k < Kq; k++)
            #pragma unroll
            for (int l = k; l < Kq; l++)
                s2[idx++] += e[k] * e[l];
    }

    __shared__ float red[44];
    if (tid < 44) red[tid] = 0.0f;
    __syncthreads();
    #pragma unroll
    for (int i = 0; i < Kq; i++) {
        float v = s1[i];
        #pragma unroll
        for (int o = 16; o; o >>= 1) v += __shfl_down_sync(0xffffffffu, v, o);
        if ((tid & 31) == 0) atomicAdd(&red[i], v);
    }
    #pragma unroll
    for (int i = 0; i < 36; i++) {
        float v = s2[i];
        #pragma unroll
        for (int o = 16; o; o >>= 1) v += __shfl_down_sync(0xffffffffu, v, o);
        if ((tid & 31) == 0) atomicAdd(&red[8 + i], v);
    }
    __syncthreads();

    if (tid < 28) {
        float* out2 = out + (size_t)BG * BINS;
        int k = 0, rem = tid;
        while (rem >= 7 - k) { rem -= 7 - k; k++; }
        int l = k + 1 + rem;
        float S1k = red[k], S1l = red[l];
        int dk = 8 + (k * (17 - k)) / 2;
        int dl = 8 + (l * (17 - l)) / 2;
        float S2kk = red[dk], S2ll = red[dl];
        int off = k * 8 - (k * (k - 1)) / 2 + (l - k);
        float S2kl = red[8 + off];
        const float Tf = (float)Tq;
        float vk = (S2kk - S1k * S1k / Tf) / (Tf - 1.0f);
        float vl = (S2ll - S1l * S1l / Tf) / (Tf - 1.0f);
        float sk = fmaxf(sqrtf(fmaxf(vk, 0.0f)), 1e-8f);
        float sl = fmaxf(sqrtf(fmaxf(vl, 0.0f)), 1e-8f);
        float corr = (S2kl - S1k * S1l / Tf) / (Tf * sk * sl);
        out2[(size_t)bg * 28 + tid] = corr;
    }
}

// ---------------- launch ----------------
extern "C" void kernel_launch(void* const* d_in, const int* in_sizes, int n_in,
                              void* d_out, int out_size) {
    const float* hs = (const float*)d_in[0];
    float* out = (float*)d_out;

    init_tables<<<16, 256>>>();
    cudaFuncSetAttribute(fwd_kernel,  cudaFuncAttributeMaxDynamicSharedMemorySize, ASMEM);
    cudaFuncSetAttribute(pair_kernel, cudaFuncAttributeMaxDynamicSharedMemorySize, BSMEM);
    fwd_kernel<<<BG, 512, ASMEM>>>(hs);
    pair_kernel<<<BG*4, 512, BSMEM>>>();
    final_kernel<<<BG, 256>>>(out);
}

// round 4
// speedup vs baseline: 1.6169x; 1.0572x over previous
#include <cuda_runtime.h>
#include <math.h>

#define Bq 16
#define Gq 32
#define Tq 4096
#define Dq 512
#define Kq 8
#define BG (Bq*Gq)          // 512
#define NWIN (Tq-3)         // 4093
#define NPAIR (NWIN-1)      // 4092
#define MPq 24
#define BINS 576

// ---------------- tables + scratch ----------------
__device__ float  g_filt[Kq*Tq];              // symmetric filters, base-8 digit-reversed, /4096 folded
__device__ float2 g_tw[512];                  // exp(-2*pi*i*m/4096), m<512 (higher powers synthesized)
__device__ int    g_lut[64];                  // 6-bit comparison key -> Lehmer pattern id
__device__ float2 g_spec[(size_t)BG*Tq];      // 16 MB spectrum (physical layout)
__device__ float  g_energy[(size_t)BG*Kq*Tq]; // 64 MB mode energies
__device__ int    g_hist[BG*BINS];

// ---------------- helpers ----------------
__device__ __forceinline__ int swb(int e){ return e ^ ((e >> 4) & 7) ^ (((e >> 6) & 1) << 3); }
__device__ __forceinline__ int swt(int m){ return m ^ ((m >> 4) & 15); }
__device__ __forceinline__ float2 cadd(float2 a, float2 b){ return make_float2(a.x+b.x, a.y+b.y); }
__device__ __forceinline__ float2 csub(float2 a, float2 b){ return make_float2(a.x-b.x, a.y-b.y); }
__device__ __forceinline__ float2 cmul(float2 a, float2 b){ return make_float2(a.x*b.x - a.y*b.y, a.x*b.y + a.y*b.x); }
__device__ __forceinline__ float2 cmulc(float2 a, float2 b){ return make_float2(a.x*b.x + a.y*b.y, a.y*b.x - a.x*b.y); }

#define CSQ2 0.70710678118654752440f

__device__ __forceinline__ void dft8_fwd(float2* x) {
    float2 t0 = cadd(x[0], x[4]), t1 = csub(x[0], x[4]);
    float2 t2 = cadd(x[2], x[6]), t3 = csub(x[2], x[6]);
    float2 s0 = cadd(x[1], x[5]), s1 = csub(x[1], x[5]);
    float2 s2 = cadd(x[3], x[7]), s3 = csub(x[3], x[7]);
    float2 E0 = cadd(t0, t2), E2 = csub(t0, t2);
    float2 E1 = make_float2(t1.x + t3.y, t1.y - t3.x);   // t1 - i t3
    float2 E3 = make_float2(t1.x - t3.y, t1.y + t3.x);
    float2 O0 = cadd(s0, s2), Oq = csub(s0, s2);
    float2 O1 = make_float2(s1.x + s3.y, s1.y - s3.x);
    float2 O3 = make_float2(s1.x - s3.y, s1.y + s3.x);
    float2 u1 = make_float2(CSQ2*(O1.x + O1.y), CSQ2*(O1.y - O1.x));   // * c(1-i)
    float2 u2 = make_float2(Oq.y, -Oq.x);                               // * -i
    float2 u3 = make_float2(CSQ2*(O3.y - O3.x), -CSQ2*(O3.x + O3.y));  // * -c(1+i)
    x[0] = cadd(E0, O0); x[4] = csub(E0, O0);
    x[1] = cadd(E1, u1); x[5] = csub(E1, u1);
    x[2] = cadd(E2, u2); x[6] = csub(E2, u2);
    x[3] = cadd(E3, u3); x[7] = csub(E3, u3);
}

__device__ __forceinline__ void dft8_inv(float2* x) {
    float2 t0 = cadd(x[0], x[4]), t1 = csub(x[0], x[4]);
    float2 t2 = cadd(x[2], x[6]), t3 = csub(x[2], x[6]);
    float2 s0 = cadd(x[1], x[5]), s1 = csub(x[1], x[5]);
    float2 s2 = cadd(x[3], x[7]), s3 = csub(x[3], x[7]);
    float2 E0 = cadd(t0, t2), E2 = csub(t0, t2);
    float2 E1 = make_float2(t1.x - t3.y, t1.y + t3.x);   // t1 + i t3
    float2 E3 = make_float2(t1.x + t3.y, t1.y - t3.x);
    float2 O0 = cadd(s0, s2), Oq = csub(s0, s2);
    float2 O1 = make_float2(s1.x - s3.y, s1.y + s3.x);
    float2 O3 = make_float2(s1.x + s3.y, s1.y - s3.x);
    float2 u1 = make_float2(CSQ2*(O1.x - O1.y), CSQ2*(O1.x + O1.y));   // * c(1+i)
    float2 u2 = make_float2(-Oq.y, Oq.x);                               // * i
    float2 u3 = make_float2(-CSQ2*(O3.x + O3.y), CSQ2*(O3.x - O3.y));  // * c(-1+i)
    x[0] = cadd(E0, O0); x[4] = csub(E0, O0);
    x[1] = cadd(E1, u1); x[5] = csub(E1, u1);
    x[2] = cadd(E2, u2); x[6] = csub(E2, u2);
    x[3] = cadd(E3, u3); x[7] = csub(E3, u3);
}

// ---------------- init ----------------
__device__ double filt_val(int idx, double cf) {
    double fr = (idx < Tq/2) ? (double)idx / Tq : (double)(idx - Tq) / Tq;
    double d = fabs(fr - cf) / 0.125;
    return exp(-0.5 * d * d);
}

__global__ void init_tables() {
    int j = blockIdx.x * blockDim.x + threadIdx.x;
    if (j < 512) {
        float a = -(float)j / 2048.0f;
        g_tw[j] = make_float2(cospif(a), sinpif(a));
    }
    if (j < Tq) {
        // base-8 digit reversal of 12-bit index (4 digits of 3 bits)
        int f = ((j & 7) << 9) | (((j >> 3) & 7) << 6) | (((j >> 6) & 7) << 3) | ((j >> 9) & 7);
        #pragma unroll
        for (int k = 0; k < Kq; k++) {
            double cf = -0.5 + (double)k / 7.0;
            double gs = 0.5 * (filt_val(f, cf) + filt_val((Tq - f) & (Tq - 1), cf));
            g_filt[k*Tq + j] = (float)(gs / (double)Tq);
        }
    }
    if (j == 0) {
        for (int q = 0; q < 64; q++) g_lut[q] = 0;
        for (int r0 = 0; r0 < 4; r0++)
        for (int r1 = 0; r1 < 4; r1++) { if (r1 == r0) continue;
        for (int r2 = 0; r2 < 4; r2++) { if (r2 == r0 || r2 == r1) continue;
            int r3 = 6 - r0 - r1 - r2;
            int rk[4] = {r0, r1, r2, r3};
            int si[4];
            for (int i = 0; i < 4; i++) si[rk[i]] = i;
            int key = (rk[0]>rk[1]) | ((rk[0]>rk[2])<<1) | ((rk[0]>rk[3])<<2)
                    | ((rk[1]>rk[2])<<3) | ((rk[1]>rk[3])<<4) | ((rk[2]>rk[3])<<5);
            int c0 = (si[0]>si[1]) + (si[0]>si[2]) + (si[0]>si[3]);
            int c1 = (si[1]>si[2]) + (si[1]>si[3]);
            int c2 = (si[2]>si[3]);
            g_lut[key] = 6*c0 + 2*c1 + c2;
        }}
    }
}

#define DSM ((Tq + 512) * 8)   // buf 4096 float2 + stw 512 float2 = 36 KB

// ---------------- kernel A: pool + forward radix-8 FFT -> g_spec ----------------
__global__ void __launch_bounds__(512, 2) fwd_kernel(const float* __restrict__ hs) {
    extern __shared__ float2 sh[];
    float2* buf = sh;
    float2* stw = sh + Tq;
    const int u = threadIdx.x;
    const int bg = blockIdx.x;
    const int b = bg >> 5, g = bg & 31;

    if (u < 512) stw[swt(u)] = g_tw[u];
    for (int i = u; i < BINS; i += 512) g_hist[bg*BINS + i] = 0;

    const float* src = hs + ((size_t)b * Tq) * Dq + g * 16;
    for (int t = u; t < Tq; t += 512) {
        const float4* p = (const float4*)(src + (size_t)t * Dq);
        float4 a = p[0], c = p[1], d = p[2], e = p[3];
        float s = a.x+a.y+a.z+a.w + c.x+c.y+c.z+c.w + d.x+d.y+d.z+d.w + e.x+e.y+e.z+e.w;
        buf[swb(t)] = make_float2(s * (1.0f/16.0f), 0.0f);
    }
    __syncthreads();

    #pragma unroll
    for (int s = 0; s < 4; s++) {
        const int h  = 512 >> (3*s);     // 512,64,8,1
        const int tm = 1 << (3*s);
        int j = u & (h - 1);
        int i = ((u ^ j) << 3) | j;
        float2 x[8];
        #pragma unroll
        for (int c = 0; c < 8; c++) x[c] = buf[swb(i + c*h)];
        dft8_fwd(x);
        if (s < 3) {
            int m = j * tm;              // < 512
            float2 w1 = stw[swt(m)];
            float2 w2 = cmul(w1, w1), w3 = cmul(w2, w1), w4 = cmul(w2, w2);
            float2 w5 = cmul(w3, w2), w6 = cmul(w3, w3), w7 = cmul(w4, w3);
            x[1] = cmul(x[1], w1); x[2] = cmul(x[2], w2); x[3] = cmul(x[3], w3);
            x[4] = cmul(x[4], w4); x[5] = cmul(x[5], w5); x[6] = cmul(x[6], w6);
            x[7] = cmul(x[7], w7);
        }
        #pragma unroll
        for (int c = 0; c < 8; c++) buf[swb(i + c*h)] = x[c];
        __syncthreads();
    }
    float2* dst = g_spec + (size_t)bg * Tq;
    for (int i = u; i < Tq; i += 512) dst[i] = buf[i];
}

// ---------------- kernel B: filter + inverse radix-8 FFT + energies + tmptm ----------------
__global__ void __launch_bounds__(512, 2) pair_kernel() {
    extern __shared__ float2 sh[];
    float2* W   = sh;
    float2* stw = sh + Tq;
    __shared__ int lut[64];
    __shared__ int hist[2*BINS];

    const int bg = blockIdx.x >> 2;
    const int p  = blockIdx.x & 3;
    const int u  = threadIdx.x;
    const int lane = u & 31;

    if (u < 512) stw[swt(u)] = g_tw[u];
    if (u < 64) lut[u] = g_lut[u];
    for (int i = u; i < 2*BINS; i += 512) hist[i] = 0;

    const float2* Xg = g_spec + (size_t)bg * Tq;
    const float* fr = g_filt + (2*p)   * Tq;
    const float* fi = g_filt + (2*p+1) * Tq;
    for (int e = u; e < Tq; e += 512) {
        float2 x = Xg[swb(e)];
        float gr = fr[e], gi = fi[e];
        W[swb(e)] = make_float2(x.x*gr - x.y*gi, x.x*gi + x.y*gr);
    }
    __syncthreads();

    #pragma unroll
    for (int s = 0; s < 4; s++) {
        const int h  = 1 << (3*s);       // 1,8,64,512
        const int tm = 512 >> (3*s);
        int j = u & (h - 1);
        int i = ((u ^ j) << 3) | j;
        float2 x[8];
        #pragma unroll
        for (int c = 0; c < 8; c++) x[c] = W[swb(i + c*h)];
        if (s > 0) {
            int m = j * tm;              // < 512
            float2 w1 = stw[swt(m)];
            float2 w2 = cmul(w1, w1), w3 = cmul(w2, w1), w4 = cmul(w2, w2);
            float2 w5 = cmul(w3, w2), w6 = cmul(w3, w3), w7 = cmul(w4, w3);
            x[1] = cmulc(x[1], w1); x[2] = cmulc(x[2], w2); x[3] = cmulc(x[3], w3);
            x[4] = cmulc(x[4], w4); x[5] = cmulc(x[5], w5); x[6] = cmulc(x[6], w6);
            x[7] = cmulc(x[7], w7);
        }
        dft8_inv(x);
        #pragma unroll
        for (int c = 0; c < 8; c++) W[swb(i + c*h)] = x[c];
        __syncthreads();
    }

    // energies (modes 2p, 2p+1)
    float* e0 = g_energy + ((size_t)bg * Kq + 2*p)     * Tq;
    float* e1 = g_energy + ((size_t)bg * Kq + 2*p + 1) * Tq;
    for (int t = u; t < Tq; t += 512) {
        float2 v = W[swb(t)];
        e0[t] = v.x * v.x;
        e1[t] = v.y * v.y;
    }

    // tmptm: single-pass register sliding window, warp-aggregated shared atomics
    {
        int* myhist = hist + ((u >> 5) & 1) * BINS;
        const int base = u * 8;
        float2 v0 = W[swb(base)], v1 = W[swb(base+1)], v2 = W[swb(base+2)], v3 = W[swb(base+3)];
        int kx = (v0.x>v1.x) | ((v0.x>v2.x)<<1) | ((v0.x>v3.x)<<2)
               | ((v1.x>v2.x)<<3) | ((v1.x>v3.x)<<4) | ((v2.x>v3.x)<<5);
        int ky = (v0.y>v1.y) | ((v0.y>v2.y)<<1) | ((v0.y>v3.y)<<2)
               | ((v1.y>v2.y)<<3) | ((v1.y>v3.y)<<4) | ((v2.y>v3.y)<<5);
        int px = lut[kx], py = lut[ky];
        #pragma unroll
        for (int i = 0; i < 8; i++) {
            int sidx = base + 4 + i; sidx = min(sidx, Tq - 1);
            float2 v4 = W[swb(sidx)];
            kx = ((kx>>3)&1) | (((kx>>4)&1)<<1) | ((v1.x>v4.x)<<2)
               | (((kx>>5)&1)<<3) | ((v2.x>v4.x)<<4) | ((v3.x>v4.x)<<5);
            ky = ((ky>>3)&1) | (((ky>>4)&1)<<1) | ((v1.y>v4.y)<<2)
               | (((ky>>5)&1)<<3) | ((v2.y>v4.y)<<4) | ((v3.y>v4.y)<<5);
            int cx = lut[kx], cy = lut[ky];
            int n = base + i;
            bool valid = (n < NPAIR);
            int linx = valid ? (px * MPq + cx) : (BINS + lane);
            unsigned mx = __match_any_sync(0xffffffffu, linx);
            if (valid && lane == (__ffs(mx) - 1)) atomicAdd(&myhist[linx], __popc(mx));
            int liny = valid ? (py * MPq + cy) : (BINS + lane);
            unsigned my = __match_any_sync(0xffffffffu, liny);
            if (valid && lane == (__ffs(my) - 1)) atomicAdd(&myhist[liny], __popc(my));
            px = cx; py = cy;
            v1 = v2; v2 = v3; v3 = v4;
        }
    }
    __syncthreads();

    for (int i = u; i < BINS; i += 512) {
        int s = hist[i] + hist[BINS + i];
        if (s) atomicAdd(&g_hist[bg*BINS + i], s);
    }
}

// ---------------- kernel C: hist normalize + fmptm ----------------
__global__ void __launch_bounds__(256, 4) final_kernel(float* __restrict__ out) {
    const int bg = blockIdx.x, tid = threadIdx.x;
    const float invs = 1.0f / (float)(Kq * NPAIR);
    for (int i = tid; i < BINS; i += 256)
        out[(size_t)bg * BINS + i] = (float)g_hist[bg*BINS + i] * invs;

    const float2* eg = (const float2*)(g_energy + (size_t)bg * Kq * Tq);
    float s1[Kq]; float s2[36];
    #pragma unroll
    for (int i = 0; i < Kq; i++) s1[i] = 0.0f;
    #pragma unroll
    for (int i = 0; i < 36; i++) s2[i] = 0.0f;

    for (int t = tid; t < Tq/2; t += 256) {
        float2 e[Kq];
        #pragma unroll
        for (int k = 0; k < Kq; k++) {
            e[k] = eg[(size_t)k * (Tq/2) + t];
            s1[k] += e[k].x + e[k].y;
        }
        int idx = 0;
        #pragma unroll
        for (int k = 0; k < Kq; k++)
            #pragma unroll
            for (int l = k; l < Kq; l++)
                s2[idx++] += e[k].x * e[l].x + e[k].y * e[l].y;
    }

    __shared__ float red[44];
    if (tid < 44) red[tid] = 0.0f;
    __syncthreads();
    #pragma unroll
    for (int i = 0; i < Kq; i++) {
        float v = s1[i];
        #pragma unroll
        for (int o = 16; o; o >>= 1) v += __shfl_down_sync(0xffffffffu, v, o);
        if ((tid & 31) == 0) atomicAdd(&red[i], v);
    }
    #pragma unroll
    for (int i = 0; i < 36; i++) {
        float v = s2[i];
        #pragma unroll
        for (int o = 16; o; o >>= 1) v += __shfl_down_sync(0xffffffffu, v, o);
        if ((tid & 31) == 0) atomicAdd(&red[8 + i], v);
    }
    __syncthreads();

    if (tid < 28) {
        float* out2 = out + (size_t)BG * BINS;
        int k = 0, rem = tid;
        while (rem >= 7 - k) { rem -= 7 - k; k++; }
        int l = k + 1 + rem;
        float S1k = red[k], S1l = red[l];
        int dk = 8 + (k * (17 - k)) / 2;
        int dl = 8 + (l * (17 - l)) / 2;
        float S2kk = red[dk], S2ll = red[dl];
        int off = k * 8 - (k * (k - 1)) / 2 + (l - k);
        float S2kl = red[8 + off];
        const float Tf = (float)Tq;
        float vk = (S2kk - S1k * S1k / Tf) / (Tf - 1.0f);
        float vl = (S2ll - S1l * S1l / Tf) / (Tf - 1.0f);
        float sk = fmaxf(sqrtf(fmaxf(vk, 0.0f)), 1e-8f);
        float sl = fmaxf(sqrtf(fmaxf(vl, 0.0f)), 1e-8f);
        float corr = (S2kl - S1k * S1l / Tf) / (Tf * sk * sl);
        out2[(size_t)bg * 28 + tid] = corr;
    }
}

// ---------------- launch ----------------
extern "C" void kernel_launch(void* const* d_in, const int* in_sizes, int n_in,
                              void* d_out, int out_size) {
    const float* hs = (const float*)d_in[0];
    float* out = (float*)d_out;

    init_tables<<<16, 256>>>();
    cudaFuncSetAttribute(fwd_kernel,  cudaFuncAttributeMaxDynamicSharedMemorySize, DSM);
    cudaFuncSetAttribute(pair_kernel, cudaFuncAttributeMaxDynamicSharedMemorySize, DSM);
    fwd_kernel<<<BG, 512, DSM>>>(hs);
    pair_kernel<<<BG*4, 512, DSM>>>();
    final_kernel<<<BG, 256>>>(out);
}